// round 14
// baseline (speedup 1.0000x reference)
#include <cuda_runtime.h>
#include <cuda_bf16.h>
#include <cuda_fp16.h>
#include <math.h>
#include <cstdint>

// ---------------- problem constants ----------------
#define B_    2
#define C_    128
#define NH_   32
#define DH_   4
#define SPAT  16384
#define NTOK  1024
#define TBL_  6727

typedef unsigned long long ull;
typedef unsigned int uint;

// ---------------- packed fp32x2 helpers ----------------
__device__ __forceinline__ ull pack2(float a) {
    ull r; uint ai = __float_as_uint(a);
    asm("mov.b64 %0, {%1, %1};" : "=l"(r) : "r"(ai));
    return r;
}
__device__ __forceinline__ ull packf2(float lo, float hi) {
    ull r;
    asm("mov.b64 %0, {%1, %2};" : "=l"(r) : "f"(lo), "f"(hi));
    return r;
}
__device__ __forceinline__ void ffma2(ull& d, ull a, ull b) {
    asm("fma.rn.f32x2 %0, %1, %2, %0;" : "+l"(d) : "l"(a), "l"(b));
}
__device__ __forceinline__ float2 unpack2(ull v) {
    float2 f; uint lo, hi;
    asm("mov.b64 {%0, %1}, %2;" : "=r"(lo), "=r"(hi) : "l"(v));
    f.x = __uint_as_float(lo); f.y = __uint_as_float(hi);
    return f;
}
__device__ __forceinline__ float ex2f(float x) {
    float r; asm("ex2.approx.f32 %0, %1;" : "=f"(r) : "f"(x)); return r;
}
// fp16x2 pack: first arg -> low half, second -> high half
__device__ __forceinline__ uint cvt_f16x2(float lo, float hi) {
    uint d;
    asm("cvt.rn.f16x2.f32 %0, %1, %2;" : "=r"(d) : "f"(hi), "f"(lo));
    return d;
}
// mma.sync m16n8k16 row.col f32.f16.f16.f32
__device__ __forceinline__ void mma16816h(float* c, const uint* a, uint b0, uint b1) {
    asm volatile(
        "mma.sync.aligned.m16n8k16.row.col.f32.f16.f16.f32 "
        "{%0,%1,%2,%3}, {%4,%5,%6,%7}, {%8,%9}, {%0,%1,%2,%3};"
        : "+f"(c[0]), "+f"(c[1]), "+f"(c[2]), "+f"(c[3])
        : "r"(a[0]), "r"(a[1]), "r"(a[2]), "r"(a[3]), "r"(b0), "r"(b1));
}
// ldmatrix 4x m8n8 b16 tiles (non-transposed)
__device__ __forceinline__ void ldsm4(uint& r0, uint& r1, uint& r2, uint& r3, uint addr) {
    asm volatile("ldmatrix.sync.aligned.m8n8.x4.shared.b16 {%0,%1,%2,%3}, [%4];"
        : "=r"(r0), "=r"(r1), "=r"(r2), "=r"(r3) : "r"(addr));
}
__device__ __forceinline__ uint smem_u32(const void* p) {
    uint a;
    asm("{ .reg .u64 t; cvta.to.shared.u64 t, %1; cvt.u32.u64 %0, t; }"
        : "=r"(a) : "l"(p));
    return a;
}

// ---------------- scratch ----------------
__device__ float g_y[3][B_][C_][SPAT];
__device__ float g_part[3][B_][NH_][256][2];
__device__ float g_stats[3][B_][NH_][2];
__device__ float g_qp[B_][NH_][NTOK][DH_];
__device__ float g_kp[B_][NH_][NTOK][DH_];
__device__ float g_vp[B_][NH_][NTOK][64];       // fp32 [n][dp]
__device__ uint  g_vh[B_ * NH_][64][512];       // fp16x2 V, [dp][m-pair]
__device__ float g_tbl2[NH_][TBL_];             // rel_table * log2(e)
__device__ uint  g_wh2[3][128 * 64];            // W hi fp16x2 [o][c-pair]
__device__ uint  g_wl2[3][128 * 64];            // W lo fp16x2
__device__ unsigned short g_idx16[NTOK * NTOK]; // rel_index as u16

// ================= K0a: split W into fp16 hi/lo pairs ========================
__global__ __launch_bounds__(256) void wprep_kernel(
    const float* __restrict__ Wq, const float* __restrict__ Wk,
    const float* __restrict__ Wv)
{
    const int proj = blockIdx.x;
    const float* W = (proj == 0) ? Wq : (proj == 1 ? Wk : Wv);
    for (int i = threadIdx.x; i < 128 * 64; i += 256) {
        int o = i >> 6, cp = i & 63;
        float v0 = W[o * 128 + 2 * cp], v1 = W[o * 128 + 2 * cp + 1];
        uint h2 = cvt_f16x2(v0, v1);
        __half2 hh = *(__half2*)&h2;
        uint l2 = cvt_f16x2(v0 - __low2float(hh), v1 - __high2float(hh));
        g_wh2[proj][i] = h2;
        g_wl2[proj][i] = l2;
    }
}

// ================= K0b: rel_index -> u16 =====================================
__global__ __launch_bounds__(256) void iprep_kernel(const int* __restrict__ rel_index)
{
    const int i = blockIdx.x * 256 + threadIdx.x;   // 262144 int4 groups
    int4 v = ((const int4*)rel_index)[i];
    ushort4 u;
    u.x = (unsigned short)v.x; u.y = (unsigned short)v.y;
    u.z = (unsigned short)v.z; u.w = (unsigned short)v.w;
    ((ushort4*)g_idx16)[i] = u;
}

// ================= K0c: prescale bias table by log2(e) =======================
__global__ __launch_bounds__(256) void tblprep_kernel(const float* __restrict__ rel_table)
{
    const int g = blockIdx.x;
    for (int i = threadIdx.x; i < TBL_; i += 256)
        g_tbl2[g][i] = rel_table[g * TBL_ + i] * 1.4426950408889634f;
}

// ================= K1: projections via mma.sync fp16 3-pass + GN partials ====
// grid (256 stiles, B, 3 proj), block 128 (4 warps). Tile 128o x 64s, K=128.
// Each warp: 32 o-rows (2 M-tiles) -> B fragments reused 2x, loaded via ldmatrix.
__global__ __launch_bounds__(128, 4) void proj_kernel(const float* __restrict__ x)
{
    __shared__ uint Xh[64 * 68];      // [s][c-pair] fp16x2 hi, stride 68 pad
    __shared__ uint Xl[64 * 68];      // lo
    __shared__ float rsum[128], rsq[128];

    const int stile = blockIdx.x, b = blockIdx.y, proj = blockIdx.z;
    const int s0 = stile * 64;
    const int tid = threadIdx.x, wid = tid >> 5, lane = tid & 31;
    const int l = lane & 3, gid = lane >> 2;
    const float* xb = x + (size_t)b * C_ * SPAT;

    // ---- produce X split tiles (transpose c-major -> [s][cp]) ----
    {
        const int s = tid & 63, cpb = tid >> 6;   // cpb 0..1
        #pragma unroll 4
        for (int it = 0; it < 32; it++) {
            int cp = cpb * 32 + it;
            float v0 = xb[(size_t)(2 * cp) * SPAT + s0 + s];
            float v1 = xb[(size_t)(2 * cp + 1) * SPAT + s0 + s];
            uint h2 = cvt_f16x2(v0, v1);
            __half2 hh = *(__half2*)&h2;
            uint l2 = cvt_f16x2(v0 - __low2float(hh), v1 - __high2float(hh));
            Xh[s * 68 + cp] = h2;
            Xl[s * 68 + cp] = l2;
        }
    }
    __syncthreads();

    // ---- mainloop: warp w -> o-rows [w*32, w*32+32), all 64 s ----
    const uint* wh = &g_wh2[proj][0];
    const uint* wl = &g_wl2[proj][0];
    const int wb = wid * 32;
    const int rA0 = wb + gid,      rB0 = rA0 + 8;    // M-tile 0
    const int rA1 = wb + 16 + gid, rB1 = rA1 + 8;    // M-tile 1

    // ldmatrix lane address offset: tile = lane/8; tiles (ntA,k0),(ntA,k1),(ntB,k0),(ntB,k1)
    const int tl = lane >> 3;
    const uint lrow = (uint)(((tl & 2) * 4 + (lane & 7)) * 272 + (tl & 1) * 16);
    const uint xh_b = smem_u32(Xh) + lrow;
    const uint xl_b = smem_u32(Xl) + lrow;

    float acc[2][8][4];
    #pragma unroll
    for (int m = 0; m < 2; m++)
        #pragma unroll
        for (int i = 0; i < 8; i++)
            #pragma unroll
            for (int j = 0; j < 4; j++) acc[m][i][j] = 0.f;

    #pragma unroll
    for (int ks = 0; ks < 8; ks++) {
        const int cp0 = ks * 8 + l, cp1 = cp0 + 4;
        uint ah0[4], al0[4], ah1[4], al1[4];
        ah0[0] = __ldg(wh + rA0 * 64 + cp0);
        ah0[1] = __ldg(wh + rB0 * 64 + cp0);
        ah0[2] = __ldg(wh + rA0 * 64 + cp1);
        ah0[3] = __ldg(wh + rB0 * 64 + cp1);
        al0[0] = __ldg(wl + rA0 * 64 + cp0);
        al0[1] = __ldg(wl + rB0 * 64 + cp0);
        al0[2] = __ldg(wl + rA0 * 64 + cp1);
        al0[3] = __ldg(wl + rB0 * 64 + cp1);
        ah1[0] = __ldg(wh + rA1 * 64 + cp0);
        ah1[1] = __ldg(wh + rB1 * 64 + cp0);
        ah1[2] = __ldg(wh + rA1 * 64 + cp1);
        ah1[3] = __ldg(wh + rB1 * 64 + cp1);
        al1[0] = __ldg(wl + rA1 * 64 + cp0);
        al1[1] = __ldg(wl + rB1 * 64 + cp0);
        al1[2] = __ldg(wl + rA1 * 64 + cp1);
        al1[3] = __ldg(wl + rB1 * 64 + cp1);

        #pragma unroll
        for (int p = 0; p < 4; p++) {
            uint bh0, bh1, bh2, bh3, bl0, bl1, bl2, bl3;
            const uint off = (uint)(p * 4352 + ks * 32);   // p*16 rows * 272B
            ldsm4(bh0, bh1, bh2, bh3, xh_b + off);
            ldsm4(bl0, bl1, bl2, bl3, xl_b + off);
            const int ntA = 2 * p, ntB = 2 * p + 1;
            mma16816h(acc[0][ntA], ah0, bh0, bh1);
            mma16816h(acc[0][ntA], ah0, bl0, bl1);
            mma16816h(acc[0][ntA], al0, bh0, bh1);
            mma16816h(acc[0][ntB], ah0, bh2, bh3);
            mma16816h(acc[0][ntB], ah0, bl2, bl3);
            mma16816h(acc[0][ntB], al0, bh2, bh3);
            mma16816h(acc[1][ntA], ah1, bh0, bh1);
            mma16816h(acc[1][ntA], ah1, bl0, bl1);
            mma16816h(acc[1][ntA], al1, bh0, bh1);
            mma16816h(acc[1][ntB], ah1, bh2, bh3);
            mma16816h(acc[1][ntB], ah1, bl2, bl3);
            mma16816h(acc[1][ntB], al1, bh2, bh3);
        }
    }

    // ---- epilogue: store y + per-row partial stats ----
    float* y = &g_y[proj][b][0][0];
    float sA[2] = {0.f, 0.f}, qA[2] = {0.f, 0.f};
    float sB[2] = {0.f, 0.f}, qB[2] = {0.f, 0.f};
    #pragma unroll
    for (int m = 0; m < 2; m++) {
        const int rA = wb + m * 16 + gid, rB = rA + 8;
        #pragma unroll
        for (int nt = 0; nt < 8; nt++) {
            float c0 = acc[m][nt][0], c1 = acc[m][nt][1];
            float c2 = acc[m][nt][2], c3 = acc[m][nt][3];
            int col = s0 + nt * 8 + 2 * l;
            *(float2*)&y[(size_t)rA * SPAT + col] = make_float2(c0, c1);
            *(float2*)&y[(size_t)rB * SPAT + col] = make_float2(c2, c3);
            sA[m] += c0 + c1; qA[m] += c0 * c0 + c1 * c1;
            sB[m] += c2 + c3; qB[m] += c2 * c2 + c3 * c3;
        }
    }
    #pragma unroll
    for (int m = 0; m < 2; m++) {
        sA[m] += __shfl_down_sync(0xffffffffu, sA[m], 1);
        sA[m] += __shfl_down_sync(0xffffffffu, sA[m], 2);
        qA[m] += __shfl_down_sync(0xffffffffu, qA[m], 1);
        qA[m] += __shfl_down_sync(0xffffffffu, qA[m], 2);
        sB[m] += __shfl_down_sync(0xffffffffu, sB[m], 1);
        sB[m] += __shfl_down_sync(0xffffffffu, sB[m], 2);
        qB[m] += __shfl_down_sync(0xffffffffu, qB[m], 1);
        qB[m] += __shfl_down_sync(0xffffffffu, qB[m], 2);
        if (l == 0) {
            int rA = wb + m * 16 + gid, rB = rA + 8;
            rsum[rA] = sA[m]; rsq[rA] = qA[m];
            rsum[rB] = sB[m]; rsq[rB] = qB[m];
        }
    }
    __syncthreads();
    if (tid < 32) {
        float S = rsum[tid * 4] + rsum[tid * 4 + 1] + rsum[tid * 4 + 2] + rsum[tid * 4 + 3];
        float Q = rsq[tid * 4] + rsq[tid * 4 + 1] + rsq[tid * 4 + 2] + rsq[tid * 4 + 3];
        g_part[proj][b][tid][stile][0] = S;
        g_part[proj][b][tid][stile][1] = Q;
    }
}

// ================= K2: finalize GN stats =====================================
__global__ __launch_bounds__(256) void stats_kernel()
{
    const int g = blockIdx.x, b = blockIdx.y, proj = blockIdx.z;
    const int tid = threadIdx.x;
    float s = g_part[proj][b][g][tid][0];
    float q = g_part[proj][b][g][tid][1];
    __shared__ float ss[8], sq[8];
    #pragma unroll
    for (int off = 16; off; off >>= 1) {
        s += __shfl_down_sync(0xffffffffu, s, off);
        q += __shfl_down_sync(0xffffffffu, q, off);
    }
    if ((tid & 31) == 0) { ss[tid >> 5] = s; sq[tid >> 5] = q; }
    __syncthreads();
    if (tid == 0) {
        float S = 0.f, Q = 0.f;
        #pragma unroll
        for (int i = 0; i < 8; i++) { S += ss[i]; Q += sq[i]; }
        const float inv = 1.f / 65536.f;
        float mu  = S * inv;
        float var = Q * inv - mu * mu;
        g_stats[proj][b][g][0] = mu;
        g_stats[proj][b][g][1] = rsqrtf(var + 1e-5f);
    }
}

// ================= K3: normalize + patchify + pool ===========================
__global__ __launch_bounds__(256) void patch_kernel(
    const float* __restrict__ gqg, const float* __restrict__ gqb,
    const float* __restrict__ gkg, const float* __restrict__ gkb,
    const float* __restrict__ gvg, const float* __restrict__ gvb)
{
    const int tid  = threadIdx.x;
    const int unit = blockIdx.x * 4 + (tid >> 6);
    const int n = unit & 1023;
    const int g = (unit >> 10) & 31;
    const int b = unit >> 15;
    const int local = tid & 63;
    const int d = local >> 4, p = local & 15;
    const int c = g * 4 + d;
    const int ti = n >> 8, hi = (n >> 4) & 15, wi = n & 15;
    const int sh = p >> 2, sw = p & 3;
    const int s = ti * 4096 + (hi * 4 + sh) * 64 + wi * 4 + sw;

    const float yq = g_y[0][b][c][s];
    const float yk = g_y[1][b][c][s];
    const float yv = g_y[2][b][c][s];

    float nq = (yq - g_stats[0][b][g][0]) * g_stats[0][b][g][1] * gqg[c] + gqb[c];
    float nk = (yk - g_stats[1][b][g][0]) * g_stats[1][b][g][1] * gkg[c] + gkb[c];
    float nv = (yv - g_stats[2][b][g][0]) * g_stats[2][b][g][1] * gvg[c] + gvb[c];

    g_vp[b][g][n][d * 16 + p] = nv;

    #pragma unroll
    for (int off = 8; off; off >>= 1) {
        nq += __shfl_down_sync(0xffffffffu, nq, off);
        nk += __shfl_down_sync(0xffffffffu, nk, off);
    }
    if (p == 0) {
        g_qp[b][g][n][d] = nq * (1.f / 16.f);
        g_kp[b][g][n][d] = nk * (1.f / 16.f);
    }
}

// ================= K3b: vp -> transposed fp16 [dp][m-pair] ===================
__global__ __launch_bounds__(256) void vtrans_kernel()
{
    __shared__ float ts[128][65];
    const int n0 = blockIdx.x * 128, bg = blockIdx.y;
    const int tid = threadIdx.x;
    const float* vp = &g_vp[0][0][0][0] + (size_t)bg * NTOK * 64;

    for (int i = tid; i < 128 * 64; i += 256) {
        int n = i >> 6, dp = i & 63;
        ts[n][dp] = vp[(size_t)(n0 + n) * 64 + dp];
    }
    __syncthreads();
    for (int i = tid; i < 64 * 64; i += 256) {
        int dp = i >> 6, j = i & 63;
        float v0 = ts[2 * j][dp], v1 = ts[2 * j + 1][dp];
        g_vh[bg][dp][(n0 >> 1) + j] = cvt_f16x2(v0, v1);
    }
}

// ================= K4: attention via mma.sync fp16 (single pass) =============
// grid (8 mtiles, 32 g, 2 b), block 256 (8 warps). 128 rows/CTA, 16 rows/warp.
// smem: kp 16KB | q 2KB | Vh 17408B = 35840B -> 3 CTAs/SM
#define ATT_SMEM 35840

__global__ __launch_bounds__(256, 3) void attn_kernel(float* __restrict__ out)
{
    extern __shared__ float smem[];
    float4* kp_s = (float4*)smem;               // 1024 float4
    float4* q_s  = (float4*)(smem + 4096);      // 128 float4 (prescaled)
    uint*   vhs  = (uint*)(smem + 4608);        // 64 rows x 68 u32 (stride pad)

    const int mtile = blockIdx.x, g = blockIdx.y, b = blockIdx.z;
    const int n0 = mtile * 128;
    const int bg = b * 32 + g;
    const int tid = threadIdx.x, wid = tid >> 5, lane = tid & 31;
    const int l = lane & 3, gid = lane >> 2;

    {
        const float4* kp = (const float4*)&g_kp[b][g][0][0];
        for (int i = tid; i < 1024; i += 256) kp_s[i] = kp[i];
        const float4* qp = (const float4*)&g_qp[b][g][0][0];
        const float QS = 0.72134752044448170f;   // 0.5 * log2(e)
        for (int i = tid; i < 128; i += 256) {
            float4 q = qp[n0 + i];
            q.x *= QS; q.y *= QS; q.z *= QS; q.w *= QS;
            q_s[i] = q;
        }
    }
    __syncthreads();

    const int rb = wid * 16;
    float4 q0 = q_s[rb + gid], q1 = q_s[rb + gid + 8];
    ull q0x = pack2(q0.x), q0y = pack2(q0.y), q0z = pack2(q0.z), q0w = pack2(q0.w);
    ull q1x = pack2(q1.x), q1y = pack2(q1.y), q1z = pack2(q1.z), q1w = pack2(q1.w);
    const float* tbl = &g_tbl2[g][0];
    const unsigned short* r0p = g_idx16 + (size_t)(n0 + rb + gid) * 1024;
    const unsigned short* r1p = r0p + 8 * 1024;

    // ldmatrix lane address offset (same geometry as proj)
    const int tl = lane >> 3;
    const uint lrow = (uint)(((tl & 2) * 4 + (lane & 7)) * 272 + (tl & 1) * 16);
    const uint vh_b = smem_u32(vhs) + lrow;

    float acc[8][4];
    #pragma unroll
    for (int i = 0; i < 8; i++)
        #pragma unroll
        for (int j = 0; j < 4; j++) acc[i][j] = 0.f;
    float s0 = 0.f, s1 = 0.f;

    for (int c = 0; c < 8; c++) {
        __syncthreads();
        for (int i = tid; i < 1024; i += 256) {
            int dp = i >> 4, j4 = i & 15;
            float4 vh = *(const float4*)&g_vh[bg][dp][c * 64 + j4 * 4];
            *(float4*)&vhs[dp * 68 + j4 * 4] = vh;
        }
        __syncthreads();

        #pragma unroll
        for (int ks = 0; ks < 8; ks++) {
            const int m00 = c * 128 + ks * 16 + 2 * l;
            float4 kv00 = kp_s[m00],     kv01 = kp_s[m00 + 1];
            float4 kv10 = kp_s[m00 + 8], kv11 = kp_s[m00 + 9];

            ushort2 iA = *(const ushort2*)(r0p + m00);
            ushort2 iB = *(const ushort2*)(r0p + m00 + 8);
            ushort2 iC = *(const ushort2*)(r1p + m00);
            ushort2 iD = *(const ushort2*)(r1p + m00 + 8);
            ull d0a = packf2(__ldg(tbl + iA.x), __ldg(tbl + iA.y));
            ull d0b = packf2(__ldg(tbl + iB.x), __ldg(tbl + iB.y));
            ull d1a = packf2(__ldg(tbl + iC.x), __ldg(tbl + iC.y));
            ull d1b = packf2(__ldg(tbl + iD.x), __ldg(tbl + iD.y));

            ull kax = packf2(kv00.x, kv01.x), kay = packf2(kv00.y, kv01.y);
            ull kaz = packf2(kv00.z, kv01.z), kaw = packf2(kv00.w, kv01.w);
            ull kbx = packf2(kv10.x, kv11.x), kby = packf2(kv10.y, kv11.y);
            ull kbz = packf2(kv10.z, kv11.z), kbw = packf2(kv10.w, kv11.w);

            ffma2(d0a, q0x, kax); ffma2(d0a, q0y, kay); ffma2(d0a, q0z, kaz); ffma2(d0a, q0w, kaw);
            ffma2(d0b, q0x, kbx); ffma2(d0b, q0y, kby); ffma2(d0b, q0z, kbz); ffma2(d0b, q0w, kbw);
            ffma2(d1a, q1x, kax); ffma2(d1a, q1y, kay); ffma2(d1a, q1z, kaz); ffma2(d1a, q1w, kaw);
            ffma2(d1b, q1x, kbx); ffma2(d1b, q1y, kby); ffma2(d1b, q1z, kbz); ffma2(d1b, q1w, kbw);

            float2 f0a = unpack2(d0a), f0b = unpack2(d0b);
            float2 f1a = unpack2(d1a), f1b = unpack2(d1b);
            float e00 = ex2f(f0a.x), e01 = ex2f(f0a.y), e02 = ex2f(f0b.x), e03 = ex2f(f0b.y);
            float e10 = ex2f(f1a.x), e11 = ex2f(f1a.y), e12 = ex2f(f1b.x), e13 = ex2f(f1b.y);
            s0 += (e00 + e01) + (e02 + e03);
            s1 += (e10 + e11) + (e12 + e13);

            uint ah[4];
            ah[0] = cvt_f16x2(e00, e01);
            ah[1] = cvt_f16x2(e10, e11);
            ah[2] = cvt_f16x2(e02, e03);
            ah[3] = cvt_f16x2(e12, e13);

            #pragma unroll
            for (int p = 0; p < 4; p++) {
                uint b0, b1, b2, b3;
                ldsm4(b0, b1, b2, b3, vh_b + (uint)(p * 4352 + ks * 32));
                mma16816h(acc[2 * p],     ah, b0, b1);
                mma16816h(acc[2 * p + 1], ah, b2, b3);
            }
        }
    }

    s0 += __shfl_xor_sync(0xffffffffu, s0, 1);
    s0 += __shfl_xor_sync(0xffffffffu, s0, 2);
    s1 += __shfl_xor_sync(0xffffffffu, s1, 1);
    s1 += __shfl_xor_sync(0xffffffffu, s1, 2);
    const float inv0 = 1.f / s0, inv1 = 1.f / s1;

    const int nrow0 = n0 + rb + gid, nrow1 = nrow0 + 8;
    const int ti0 = nrow0 >> 8, hi0 = (nrow0 >> 4) & 15, wi0 = nrow0 & 15;
    const int ti1 = nrow1 >> 8, hi1 = (nrow1 >> 4) & 15, wi1 = nrow1 & 15;
    #pragma unroll
    for (int nb = 0; nb < 8; nb++) {
        const int dp = nb * 8 + 2 * l;
        const int d = dp >> 4, p = dp & 15, sh = p >> 2, sw = p & 3;
        const int cch = (b * 128 + g * 4 + d);
        size_t o0 = ((size_t)(cch * 4 + ti0) * 64 + hi0 * 4 + sh) * 64 + wi0 * 4 + sw;
        size_t o1 = ((size_t)(cch * 4 + ti1) * 64 + hi1 * 4 + sh) * 64 + wi1 * 4 + sw;
        float2 v0 = make_float2(acc[nb][0] * inv0, acc[nb][1] * inv0);
        float2 v1 = make_float2(acc[nb][2] * inv1, acc[nb][3] * inv1);
        *(float2*)&out[o0] = v0;
        *(float2*)&out[o1] = v1;
    }
}

// ============================ launcher =======================================
extern "C" void kernel_launch(void* const* d_in, const int* in_sizes, int n_in,
                              void* d_out, int out_size)
{
    const float* x   = (const float*)d_in[0];
    const float* Wq  = (const float*)d_in[1];
    const float* Wk  = (const float*)d_in[2];
    const float* Wv  = (const float*)d_in[3];
    const float* gqg = (const float*)d_in[4];
    const float* gqb = (const float*)d_in[5];
    const float* gkg = (const float*)d_in[6];
    const float* gkb = (const float*)d_in[7];
    const float* gvg = (const float*)d_in[8];
    const float* gvb = (const float*)d_in[9];
    const float* rel_table = (const float*)d_in[10];
    const int*   rel_index = (const int*)d_in[11];
    float* out = (float*)d_out;

    cudaFuncSetAttribute(attn_kernel, cudaFuncAttributeMaxDynamicSharedMemorySize, ATT_SMEM);

    wprep_kernel<<<3, 256>>>(Wq, Wk, Wv);
    iprep_kernel<<<1024, 256>>>(rel_index);
    tblprep_kernel<<<NH_, 256>>>(rel_table);
    proj_kernel<<<dim3(256, B_, 3), 128>>>(x);
    stats_kernel<<<dim3(NH_, B_, 3), 256>>>();
    patch_kernel<<<16384, 256>>>(gqg, gqb, gkg, gkb, gvg, gvb);
    vtrans_kernel<<<dim3(8, 64), 256>>>();
    attn_kernel<<<dim3(8, NH_, B_), 256, ATT_SMEM>>>(out);
}

// round 15
// speedup vs baseline: 1.0632x; 1.0632x over previous
#include <cuda_runtime.h>
#include <cuda_bf16.h>
#include <cuda_fp16.h>
#include <math.h>
#include <cstdint>

// ---------------- problem constants ----------------
#define B_    2
#define C_    128
#define NH_   32
#define DH_   4
#define SPAT  16384
#define NTOK  1024
#define TBL_  6727

typedef unsigned long long ull;
typedef unsigned int uint;

// ---------------- packed fp32x2 helpers ----------------
__device__ __forceinline__ ull pack2(float a) {
    ull r; uint ai = __float_as_uint(a);
    asm("mov.b64 %0, {%1, %1};" : "=l"(r) : "r"(ai));
    return r;
}
__device__ __forceinline__ ull packf2(float lo, float hi) {
    ull r;
    asm("mov.b64 %0, {%1, %2};" : "=l"(r) : "f"(lo), "f"(hi));
    return r;
}
__device__ __forceinline__ void ffma2(ull& d, ull a, ull b) {
    asm("fma.rn.f32x2 %0, %1, %2, %0;" : "+l"(d) : "l"(a), "l"(b));
}
__device__ __forceinline__ float2 unpack2(ull v) {
    float2 f; uint lo, hi;
    asm("mov.b64 {%0, %1}, %2;" : "=r"(lo), "=r"(hi) : "l"(v));
    f.x = __uint_as_float(lo); f.y = __uint_as_float(hi);
    return f;
}
__device__ __forceinline__ float ex2f(float x) {
    float r; asm("ex2.approx.f32 %0, %1;" : "=f"(r) : "f"(x)); return r;
}
// fp16x2 pack: first arg -> low half, second -> high half
__device__ __forceinline__ uint cvt_f16x2(float lo, float hi) {
    uint d;
    asm("cvt.rn.f16x2.f32 %0, %1, %2;" : "=r"(d) : "f"(hi), "f"(lo));
    return d;
}
// mma.sync m16n8k16 row.col f32.f16.f16.f32
__device__ __forceinline__ void mma16816h(float* c, const uint* a, uint b0, uint b1) {
    asm volatile(
        "mma.sync.aligned.m16n8k16.row.col.f32.f16.f16.f32 "
        "{%0,%1,%2,%3}, {%4,%5,%6,%7}, {%8,%9}, {%0,%1,%2,%3};"
        : "+f"(c[0]), "+f"(c[1]), "+f"(c[2]), "+f"(c[3])
        : "r"(a[0]), "r"(a[1]), "r"(a[2]), "r"(a[3]), "r"(b0), "r"(b1));
}

// ---------------- scratch ----------------
__device__ __half g_yh[3][B_][C_][SPAT];        // fp16 projections (25 MB)
__device__ float  g_part[3][B_][NH_][256][2];
__device__ float  g_stats[3][B_][NH_][2];
__device__ float  g_qp[B_][NH_][NTOK][DH_];
__device__ float  g_kp[B_][NH_][NTOK][DH_];
__device__ __half g_vf[B_][NH_][NTOK][64];      // fp16 V [n][dp] (8 MB)
__device__ uint   g_vh[B_ * NH_][64][512];      // fp16x2 V, [dp][m-pair] (16 MB)
__device__ float  g_tbl2[NH_][TBL_];            // rel_table * log2(e)
__device__ uint   g_wh2[3][128 * 64];           // W hi fp16x2 [o][c-pair]
__device__ uint   g_wl2[3][128 * 64];           // W lo fp16x2
__device__ __half g_bias[NH_][NTOK][NTOK];      // pre-expanded bias*log2e (64 MB)

// ================= K0a: split W into fp16 hi/lo pairs ========================
__global__ __launch_bounds__(256) void wprep_kernel(
    const float* __restrict__ Wq, const float* __restrict__ Wk,
    const float* __restrict__ Wv)
{
    const int proj = blockIdx.x;
    const float* W = (proj == 0) ? Wq : (proj == 1 ? Wk : Wv);
    for (int i = threadIdx.x; i < 128 * 64; i += 256) {
        int o = i >> 6, cp = i & 63;
        float v0 = W[o * 128 + 2 * cp], v1 = W[o * 128 + 2 * cp + 1];
        uint h2 = cvt_f16x2(v0, v1);
        __half2 hh = *(__half2*)&h2;
        uint l2 = cvt_f16x2(v0 - __low2float(hh), v1 - __high2float(hh));
        g_wh2[proj][i] = h2;
        g_wl2[proj][i] = l2;
    }
}

// ================= K0c: prescale bias table by log2(e) =======================
__global__ __launch_bounds__(256) void tblprep_kernel(const float* __restrict__ rel_table)
{
    const int g = blockIdx.x;
    for (int i = threadIdx.x; i < TBL_; i += 256)
        g_tbl2[g][i] = rel_table[g * TBL_ + i] * 1.4426950408889634f;
}

// ================= K0d: expand bias table -> fp16 [g][n][m] ==================
// grid 1024 (one n-row per block). Gathers are along consecutive m -> mostly
// consecutive idx -> few L1tex wavefronts. Shared by both batches in attn.
__global__ __launch_bounds__(256) void bexp_kernel(const int* __restrict__ rel_index)
{
    __shared__ unsigned short sidx[1024];
    const int n = blockIdx.x;
    const int tid = threadIdx.x;
    for (int i = tid; i < 1024; i += 256)
        sidx[i] = (unsigned short)rel_index[n * 1024 + i];
    __syncthreads();
    #pragma unroll 1
    for (int g = 0; g < 32; g++) {
        const float* t = &g_tbl2[g][0];
        __half2* dst = (__half2*)&g_bias[g][n][0];
        #pragma unroll
        for (int it = 0; it < 2; it++) {
            int i = tid + it * 256;
            float b0 = __ldg(t + sidx[2 * i]);
            float b1 = __ldg(t + sidx[2 * i + 1]);
            dst[i] = __floats2half2_rn(b0, b1);
        }
    }
}

// ================= K1: projections via mma.sync fp16 3-pass + GN partials ====
// grid (256 stiles, B, 3 proj), block 256 (8 warps). Tile 128o x 64s, K=128.
__global__ __launch_bounds__(256) void proj_kernel(const float* __restrict__ x)
{
    __shared__ uint Xh[64 * 68];      // [s][c-pair] fp16x2 hi, stride 68 pad
    __shared__ uint Xl[64 * 68];      // lo
    __shared__ float rsum[128], rsq[128];

    const int stile = blockIdx.x, b = blockIdx.y, proj = blockIdx.z;
    const int s0 = stile * 64;
    const int tid = threadIdx.x, wid = tid >> 5, lane = tid & 31;
    const int l = lane & 3, gid = lane >> 2;
    const float* xb = x + (size_t)b * C_ * SPAT;

    // ---- produce X split tiles (transpose c-major -> [s][cp]) ----
    {
        const int s = tid & 63, cpb = tid >> 6;
        #pragma unroll 4
        for (int it = 0; it < 16; it++) {
            int cp = cpb * 16 + it;
            float v0 = xb[(size_t)(2 * cp) * SPAT + s0 + s];
            float v1 = xb[(size_t)(2 * cp + 1) * SPAT + s0 + s];
            uint h2 = cvt_f16x2(v0, v1);
            __half2 hh = *(__half2*)&h2;
            uint l2 = cvt_f16x2(v0 - __low2float(hh), v1 - __high2float(hh));
            Xh[s * 68 + cp] = h2;
            Xl[s * 68 + cp] = l2;
        }
    }
    __syncthreads();

    // ---- mainloop: warp w -> o-rows [w*16, w*16+16), all 64 s ----
    const uint* wh = &g_wh2[proj][0];
    const uint* wl = &g_wl2[proj][0];
    const int ob = wid * 16;
    const int row0 = ob + gid, row1 = row0 + 8;

    float acc[8][4];
    #pragma unroll
    for (int i = 0; i < 8; i++)
        #pragma unroll
        for (int j = 0; j < 4; j++) acc[i][j] = 0.f;

    #pragma unroll
    for (int ks = 0; ks < 8; ks++) {
        const int cp0 = ks * 8 + l, cp1 = cp0 + 4;
        uint ahi[4], alo[4];
        ahi[0] = __ldg(wh + row0 * 64 + cp0);
        ahi[1] = __ldg(wh + row1 * 64 + cp0);
        ahi[2] = __ldg(wh + row0 * 64 + cp1);
        ahi[3] = __ldg(wh + row1 * 64 + cp1);
        alo[0] = __ldg(wl + row0 * 64 + cp0);
        alo[1] = __ldg(wl + row1 * 64 + cp0);
        alo[2] = __ldg(wl + row0 * 64 + cp1);
        alo[3] = __ldg(wl + row1 * 64 + cp1);
        #pragma unroll
        for (int nt = 0; nt < 8; nt++) {
            const uint* bp = Xh + (nt * 8 + gid) * 68 + cp0;
            const uint* bq = Xl + (nt * 8 + gid) * 68 + cp0;
            uint b0h = bp[0], b1h = bp[4];
            uint b0l = bq[0], b1l = bq[4];
            mma16816h(acc[nt], ahi, b0h, b1h);
            mma16816h(acc[nt], ahi, b0l, b1l);
            mma16816h(acc[nt], alo, b0h, b1h);
        }
    }

    // ---- epilogue: store y (fp16) + per-row partial stats (from fp32 accs) ----
    __half* y = &g_yh[proj][b][0][0];
    float s_r0 = 0.f, q_r0 = 0.f, s_r1 = 0.f, q_r1 = 0.f;
    #pragma unroll
    for (int nt = 0; nt < 8; nt++) {
        float c0 = acc[nt][0], c1 = acc[nt][1], c2 = acc[nt][2], c3 = acc[nt][3];
        int col = s0 + nt * 8 + 2 * l;
        *(__half2*)&y[(size_t)row0 * SPAT + col] = __floats2half2_rn(c0, c1);
        *(__half2*)&y[(size_t)row1 * SPAT + col] = __floats2half2_rn(c2, c3);
        s_r0 += c0 + c1; q_r0 += c0 * c0 + c1 * c1;
        s_r1 += c2 + c3; q_r1 += c2 * c2 + c3 * c3;
    }
    // quad reduce (lanes gid*4 + l, l = 0..3)
    s_r0 += __shfl_down_sync(0xffffffffu, s_r0, 1);
    s_r0 += __shfl_down_sync(0xffffffffu, s_r0, 2);
    q_r0 += __shfl_down_sync(0xffffffffu, q_r0, 1);
    q_r0 += __shfl_down_sync(0xffffffffu, q_r0, 2);
    s_r1 += __shfl_down_sync(0xffffffffu, s_r1, 1);
    s_r1 += __shfl_down_sync(0xffffffffu, s_r1, 2);
    q_r1 += __shfl_down_sync(0xffffffffu, q_r1, 1);
    q_r1 += __shfl_down_sync(0xffffffffu, q_r1, 2);
    if (l == 0) {
        rsum[row0] = s_r0; rsq[row0] = q_r0;
        rsum[row1] = s_r1; rsq[row1] = q_r1;
    }
    __syncthreads();
    if (tid < 32) {
        float S = rsum[tid * 4] + rsum[tid * 4 + 1] + rsum[tid * 4 + 2] + rsum[tid * 4 + 3];
        float Q = rsq[tid * 4] + rsq[tid * 4 + 1] + rsq[tid * 4 + 2] + rsq[tid * 4 + 3];
        g_part[proj][b][tid][stile][0] = S;
        g_part[proj][b][tid][stile][1] = Q;
    }
}

// ================= K2: finalize GN stats =====================================
__global__ __launch_bounds__(256) void stats_kernel()
{
    const int g = blockIdx.x, b = blockIdx.y, proj = blockIdx.z;
    const int tid = threadIdx.x;
    float s = g_part[proj][b][g][tid][0];
    float q = g_part[proj][b][g][tid][1];
    __shared__ float ss[8], sq[8];
    #pragma unroll
    for (int off = 16; off; off >>= 1) {
        s += __shfl_down_sync(0xffffffffu, s, off);
        q += __shfl_down_sync(0xffffffffu, q, off);
    }
    if ((tid & 31) == 0) { ss[tid >> 5] = s; sq[tid >> 5] = q; }
    __syncthreads();
    if (tid == 0) {
        float S = 0.f, Q = 0.f;
        #pragma unroll
        for (int i = 0; i < 8; i++) { S += ss[i]; Q += sq[i]; }
        const float inv = 1.f / 65536.f;
        float mu  = S * inv;
        float var = Q * inv - mu * mu;
        g_stats[proj][b][g][0] = mu;
        g_stats[proj][b][g][1] = rsqrtf(var + 1e-5f);
    }
}

// ================= K3: normalize + patchify + pool ===========================
__global__ __launch_bounds__(256) void patch_kernel(
    const float* __restrict__ gqg, const float* __restrict__ gqb,
    const float* __restrict__ gkg, const float* __restrict__ gkb,
    const float* __restrict__ gvg, const float* __restrict__ gvb)
{
    const int tid  = threadIdx.x;
    const int unit = blockIdx.x * 4 + (tid >> 6);
    const int n = unit & 1023;
    const int g = (unit >> 10) & 31;
    const int b = unit >> 15;
    const int local = tid & 63;
    const int d = local >> 4, p = local & 15;
    const int c = g * 4 + d;
    const int ti = n >> 8, hi = (n >> 4) & 15, wi = n & 15;
    const int sh = p >> 2, sw = p & 3;
    const int s = ti * 4096 + (hi * 4 + sh) * 64 + wi * 4 + sw;

    const float yq = __half2float(g_yh[0][b][c][s]);
    const float yk = __half2float(g_yh[1][b][c][s]);
    const float yv = __half2float(g_yh[2][b][c][s]);

    float nq = (yq - g_stats[0][b][g][0]) * g_stats[0][b][g][1] * gqg[c] + gqb[c];
    float nk = (yk - g_stats[1][b][g][0]) * g_stats[1][b][g][1] * gkg[c] + gkb[c];
    float nv = (yv - g_stats[2][b][g][0]) * g_stats[2][b][g][1] * gvg[c] + gvb[c];

    g_vf[b][g][n][d * 16 + p] = __float2half(nv);

    #pragma unroll
    for (int off = 8; off; off >>= 1) {
        nq += __shfl_down_sync(0xffffffffu, nq, off);
        nk += __shfl_down_sync(0xffffffffu, nk, off);
    }
    if (p == 0) {
        g_qp[b][g][n][d] = nq * (1.f / 16.f);
        g_kp[b][g][n][d] = nk * (1.f / 16.f);
    }
}

// ================= K3b: vp -> transposed fp16 [dp][m-pair] ===================
__global__ __launch_bounds__(256) void vtrans_kernel()
{
    __shared__ float ts[128][65];
    const int n0 = blockIdx.x * 128, bg = blockIdx.y;
    const int tid = threadIdx.x;
    const __half* vp = &g_vf[0][0][0][0] + (size_t)bg * NTOK * 64;

    for (int i = tid; i < 128 * 64; i += 256) {
        int n = i >> 6, dp = i & 63;
        ts[n][dp] = __half2float(vp[(size_t)(n0 + n) * 64 + dp]);
    }
    __syncthreads();
    for (int i = tid; i < 64 * 64; i += 256) {
        int dp = i >> 6, j = i & 63;
        float v0 = ts[2 * j][dp], v1 = ts[2 * j + 1][dp];
        g_vh[bg][dp][(n0 >> 1) + j] = cvt_f16x2(v0, v1);
    }
}

// ================= K4: attention via mma.sync fp16 (single pass) =============
// grid (8 mtiles, 32 g, 2 b), block 256 (8 warps). 128 rows/CTA, 16 rows/warp.
// Bias comes from pre-expanded g_bias (contiguous loads, NO gathers).
// smem: kp 16KB | q 2KB | Vh 17408B = 35840B -> 3 CTAs/SM
#define ATT_SMEM 35840

__global__ __launch_bounds__(256, 3) void attn_kernel(float* __restrict__ out)
{
    extern __shared__ float smem[];
    float4* kp_s = (float4*)smem;               // 1024 float4
    float4* q_s  = (float4*)(smem + 4096);      // 128 float4 (prescaled)
    uint*   vhs  = (uint*)(smem + 4608);        // 64 rows x 68 u32 (stride pad)

    const int mtile = blockIdx.x, g = blockIdx.y, b = blockIdx.z;
    const int n0 = mtile * 128;
    const int bg = b * 32 + g;
    const int tid = threadIdx.x, wid = tid >> 5, lane = tid & 31;
    const int l = lane & 3, gid = lane >> 2;

    {
        const float4* kp = (const float4*)&g_kp[b][g][0][0];
        for (int i = tid; i < 1024; i += 256) kp_s[i] = kp[i];
        const float4* qp = (const float4*)&g_qp[b][g][0][0];
        const float QS = 0.72134752044448170f;   // 0.5 * log2(e)
        for (int i = tid; i < 128; i += 256) {
            float4 q = qp[n0 + i];
            q.x *= QS; q.y *= QS; q.z *= QS; q.w *= QS;
            q_s[i] = q;
        }
    }
    __syncthreads();

    const int rb = wid * 16;
    float4 q0 = q_s[rb + gid], q1 = q_s[rb + gid + 8];
    ull q0x = pack2(q0.x), q0y = pack2(q0.y), q0z = pack2(q0.z), q0w = pack2(q0.w);
    ull q1x = pack2(q1.x), q1y = pack2(q1.y), q1z = pack2(q1.z), q1w = pack2(q1.w);
    const __half* b0p = &g_bias[g][n0 + rb + gid][0];
    const __half* b1p = b0p + 8 * 1024;

    float acc[8][4];
    #pragma unroll
    for (int i = 0; i < 8; i++)
        #pragma unroll
        for (int j = 0; j < 4; j++) acc[i][j] = 0.f;
    float s0 = 0.f, s1 = 0.f;

    for (int c = 0; c < 8; c++) {
        __syncthreads();
        for (int i = tid; i < 1024; i += 256) {
            int dp = i >> 4, j4 = i & 15;
            float4 vh = *(const float4*)&g_vh[bg][dp][c * 64 + j4 * 4];
            *(float4*)&vhs[dp * 68 + j4 * 4] = vh;
        }
        __syncthreads();

        #pragma unroll
        for (int ks = 0; ks < 8; ks++) {
            const int m00 = c * 128 + ks * 16 + 2 * l;
            float4 kv00 = kp_s[m00],     kv01 = kp_s[m00 + 1];
            float4 kv10 = kp_s[m00 + 8], kv11 = kp_s[m00 + 9];

            float2 fA = __half22float2(__ldg((const __half2*)(b0p + m00)));
            float2 fB = __half22float2(__ldg((const __half2*)(b0p + m00 + 8)));
            float2 fC = __half22float2(__ldg((const __half2*)(b1p + m00)));
            float2 fD = __half22float2(__ldg((const __half2*)(b1p + m00 + 8)));
            ull d0a = packf2(fA.x, fA.y);
            ull d0b = packf2(fB.x, fB.y);
            ull d1a = packf2(fC.x, fC.y);
            ull d1b = packf2(fD.x, fD.y);

            ull kax = packf2(kv00.x, kv01.x), kay = packf2(kv00.y, kv01.y);
            ull kaz = packf2(kv00.z, kv01.z), kaw = packf2(kv00.w, kv01.w);
            ull kbx = packf2(kv10.x, kv11.x), kby = packf2(kv10.y, kv11.y);
            ull kbz = packf2(kv10.z, kv11.z), kbw = packf2(kv10.w, kv11.w);

            ffma2(d0a, q0x, kax); ffma2(d0a, q0y, kay); ffma2(d0a, q0z, kaz); ffma2(d0a, q0w, kaw);
            ffma2(d0b, q0x, kbx); ffma2(d0b, q0y, kby); ffma2(d0b, q0z, kbz); ffma2(d0b, q0w, kbw);
            ffma2(d1a, q1x, kax); ffma2(d1a, q1y, kay); ffma2(d1a, q1z, kaz); ffma2(d1a, q1w, kaw);
            ffma2(d1b, q1x, kbx); ffma2(d1b, q1y, kby); ffma2(d1b, q1z, kbz); ffma2(d1b, q1w, kbw);

            float2 f0a = unpack2(d0a), f0b = unpack2(d0b);
            float2 f1a = unpack2(d1a), f1b = unpack2(d1b);
            float e00 = ex2f(f0a.x), e01 = ex2f(f0a.y), e02 = ex2f(f0b.x), e03 = ex2f(f0b.y);
            float e10 = ex2f(f1a.x), e11 = ex2f(f1a.y), e12 = ex2f(f1b.x), e13 = ex2f(f1b.y);
            s0 += (e00 + e01) + (e02 + e03);
            s1 += (e10 + e11) + (e12 + e13);

            uint ah[4];
            ah[0] = cvt_f16x2(e00, e01);
            ah[1] = cvt_f16x2(e10, e11);
            ah[2] = cvt_f16x2(e02, e03);
            ah[3] = cvt_f16x2(e12, e13);

            const uint* bh = vhs + ks * 8 + l;
            #pragma unroll
            for (int nb = 0; nb < 8; nb++) {
                int ro = (nb * 8 + gid) * 68;
                mma16816h(acc[nb], ah, bh[ro], bh[ro + 4]);
            }
        }
    }

    s0 += __shfl_xor_sync(0xffffffffu, s0, 1);
    s0 += __shfl_xor_sync(0xffffffffu, s0, 2);
    s1 += __shfl_xor_sync(0xffffffffu, s1, 1);
    s1 += __shfl_xor_sync(0xffffffffu, s1, 2);
    const float inv0 = 1.f / s0, inv1 = 1.f / s1;

    const int nrow0 = n0 + rb + gid, nrow1 = nrow0 + 8;
    const int ti0 = nrow0 >> 8, hi0 = (nrow0 >> 4) & 15, wi0 = nrow0 & 15;
    const int ti1 = nrow1 >> 8, hi1 = (nrow1 >> 4) & 15, wi1 = nrow1 & 15;
    #pragma unroll
    for (int nb = 0; nb < 8; nb++) {
        const int dp = nb * 8 + 2 * l;
        const int d = dp >> 4, p = dp & 15, sh = p >> 2, sw = p & 3;
        const int cch = (b * 128 + g * 4 + d);
        size_t o0 = ((size_t)(cch * 4 + ti0) * 64 + hi0 * 4 + sh) * 64 + wi0 * 4 + sw;
        size_t o1 = ((size_t)(cch * 4 + ti1) * 64 + hi1 * 4 + sh) * 64 + wi1 * 4 + sw;
        float2 v0 = make_float2(acc[nb][0] * inv0, acc[nb][1] * inv0);
        float2 v1 = make_float2(acc[nb][2] * inv1, acc[nb][3] * inv1);
        *(float2*)&out[o0] = v0;
        *(float2*)&out[o1] = v1;
    }
}

// ============================ launcher =======================================
extern "C" void kernel_launch(void* const* d_in, const int* in_sizes, int n_in,
                              void* d_out, int out_size)
{
    const float* x   = (const float*)d_in[0];
    const float* Wq  = (const float*)d_in[1];
    const float* Wk  = (const float*)d_in[2];
    const float* Wv  = (const float*)d_in[3];
    const float* gqg = (const float*)d_in[4];
    const float* gqb = (const float*)d_in[5];
    const float* gkg = (const float*)d_in[6];
    const float* gkb = (const float*)d_in[7];
    const float* gvg = (const float*)d_in[8];
    const float* gvb = (const float*)d_in[9];
    const float* rel_table = (const float*)d_in[10];
    const int*   rel_index = (const int*)d_in[11];
    float* out = (float*)d_out;

    cudaFuncSetAttribute(attn_kernel, cudaFuncAttributeMaxDynamicSharedMemorySize, ATT_SMEM);

    wprep_kernel<<<3, 256>>>(Wq, Wk, Wv);
    tblprep_kernel<<<NH_, 256>>>(rel_table);
    bexp_kernel<<<1024, 256>>>(rel_index);
    proj_kernel<<<dim3(256, B_, 3), 256>>>(x);
    stats_kernel<<<dim3(NH_, B_, 3), 256>>>();
    patch_kernel<<<16384, 256>>>(gqg, gqb, gkg, gkb, gvg, gvb);
    vtrans_kernel<<<dim3(8, 64), 256>>>();
    attn_kernel<<<dim3(8, NH_, B_), 256, ATT_SMEM>>>(out);
}

// round 16
// speedup vs baseline: 1.1519x; 1.0833x over previous
#include <cuda_runtime.h>
#include <cuda_bf16.h>
#include <cuda_fp16.h>
#include <math.h>
#include <cstdint>

// ---------------- problem constants ----------------
#define B_    2
#define C_    128
#define NH_   32
#define DH_   4
#define SPAT  16384
#define NTOK  1024
#define TBL_  6727

typedef unsigned long long ull;
typedef unsigned int uint;

// ---------------- packed fp32x2 helpers ----------------
__device__ __forceinline__ ull pack2(float a) {
    ull r; uint ai = __float_as_uint(a);
    asm("mov.b64 %0, {%1, %1};" : "=l"(r) : "r"(ai));
    return r;
}
__device__ __forceinline__ ull packf2(float lo, float hi) {
    ull r;
    asm("mov.b64 %0, {%1, %2};" : "=l"(r) : "f"(lo), "f"(hi));
    return r;
}
__device__ __forceinline__ void ffma2(ull& d, ull a, ull b) {
    asm("fma.rn.f32x2 %0, %1, %2, %0;" : "+l"(d) : "l"(a), "l"(b));
}
__device__ __forceinline__ float2 unpack2(ull v) {
    float2 f; uint lo, hi;
    asm("mov.b64 {%0, %1}, %2;" : "=r"(lo), "=r"(hi) : "l"(v));
    f.x = __uint_as_float(lo); f.y = __uint_as_float(hi);
    return f;
}
__device__ __forceinline__ float ex2f(float x) {
    float r; asm("ex2.approx.f32 %0, %1;" : "=f"(r) : "f"(x)); return r;
}
// fp16x2 pack: first arg -> low half, second -> high half
__device__ __forceinline__ uint cvt_f16x2(float lo, float hi) {
    uint d;
    asm("cvt.rn.f16x2.f32 %0, %1, %2;" : "=r"(d) : "f"(hi), "f"(lo));
    return d;
}
// mma.sync m16n8k16 row.col f32.f16.f16.f32
__device__ __forceinline__ void mma16816h(float* c, const uint* a, uint b0, uint b1) {
    asm volatile(
        "mma.sync.aligned.m16n8k16.row.col.f32.f16.f16.f32 "
        "{%0,%1,%2,%3}, {%4,%5,%6,%7}, {%8,%9}, {%0,%1,%2,%3};"
        : "+f"(c[0]), "+f"(c[1]), "+f"(c[2]), "+f"(c[3])
        : "r"(a[0]), "r"(a[1]), "r"(a[2]), "r"(a[3]), "r"(b0), "r"(b1));
}

// ---------------- scratch ----------------
__device__ __half g_yh[3][B_][C_][SPAT];        // fp16 projections (25 MB)
__device__ float  g_part[3][B_][NH_][256][2];
__device__ float  g_stats[3][B_][NH_][2];
__device__ float  g_qp[B_][NH_][NTOK][DH_];
__device__ float  g_kp[B_][NH_][NTOK][DH_];
__device__ __half g_vf[B_][NH_][NTOK][64];      // fp16 V [n][dp] (8 MB)
__device__ uint   g_vh[B_ * NH_][64][512];      // fp16x2 V, [dp][m-pair] (16 MB)
__device__ float  g_tbl2[NH_][TBL_];            // rel_table * log2(e)
__device__ uint   g_wh2[3][128 * 64];           // W hi fp16x2 [o][c-pair]
__device__ uint   g_wl2[3][128 * 64];           // W lo fp16x2
__device__ uint4  g_wfh[3][8][8][32];           // W hi fragments [proj][ob][ks][lane]
__device__ uint4  g_wfl[3][8][8][32];           // W lo fragments
__device__ uint4  g_bfrag[NH_][64][64][32];     // bias fragments [g][rowblk][ksg][lane] (67 MB)

// ================= K0a: split W into fp16 hi/lo pairs ========================
__global__ __launch_bounds__(256) void wprep_kernel(
    const float* __restrict__ Wq, const float* __restrict__ Wk,
    const float* __restrict__ Wv)
{
    const int proj = blockIdx.x;
    const float* W = (proj == 0) ? Wq : (proj == 1 ? Wk : Wv);
    for (int i = threadIdx.x; i < 128 * 64; i += 256) {
        int o = i >> 6, cp = i & 63;
        float v0 = W[o * 128 + 2 * cp], v1 = W[o * 128 + 2 * cp + 1];
        uint h2 = cvt_f16x2(v0, v1);
        __half2 hh = *(__half2*)&h2;
        uint l2 = cvt_f16x2(v0 - __low2float(hh), v1 - __high2float(hh));
        g_wh2[proj][i] = h2;
        g_wl2[proj][i] = l2;
    }
}

// ================= K0b: W -> fragment-major layout ===========================
// grid (3, 8 ob), block 256 = 8 ks x 32 lanes
__global__ __launch_bounds__(256) void wfrag_kernel()
{
    const int proj = blockIdx.x, ob = blockIdx.y;
    const int tid = threadIdx.x;
    const int ks = tid >> 5, lane = tid & 31;
    const int gid = lane >> 2, l = lane & 3;
    const int row0 = ob * 16 + gid, row1 = row0 + 8;
    const int cp0 = ks * 8 + l, cp1 = cp0 + 4;
    uint4 h, lo;
    h.x  = g_wh2[proj][row0 * 64 + cp0];
    h.y  = g_wh2[proj][row1 * 64 + cp0];
    h.z  = g_wh2[proj][row0 * 64 + cp1];
    h.w  = g_wh2[proj][row1 * 64 + cp1];
    lo.x = g_wl2[proj][row0 * 64 + cp0];
    lo.y = g_wl2[proj][row1 * 64 + cp0];
    lo.z = g_wl2[proj][row0 * 64 + cp1];
    lo.w = g_wl2[proj][row1 * 64 + cp1];
    g_wfh[proj][ob][ks][lane] = h;
    g_wfl[proj][ob][ks][lane] = lo;
}

// ================= K0c: prescale bias table by log2(e) =======================
__global__ __launch_bounds__(256) void tblprep_kernel(const float* __restrict__ rel_table)
{
    const int g = blockIdx.x;
    for (int i = threadIdx.x; i < TBL_; i += 256)
        g_tbl2[g][i] = rel_table[g * TBL_ + i] * 1.4426950408889634f;
}

// ================= K0d: expand bias -> fragment-major fp16 ===================
// grid (64 rowblocks, 2 mhalves, 4 g-quads), block 256.
// dyn smem: sidx u16[16][512] (16KB) + stage half2[16][260] (16.25KB)
#define BEXP_SMEM (16384 + 16640)
__global__ __launch_bounds__(256) void bexp_kernel(const int* __restrict__ rel_index)
{
    extern __shared__ char bsm[];
    unsigned short* sidx = (unsigned short*)bsm;          // [16][512]
    __half2* stage = (__half2*)(bsm + 16384);             // [16][260] stride 260

    const int rowblk = blockIdx.x, mhalf = blockIdx.y;
    const int tid = threadIdx.x;

    // load idx (coalesced int4)
    for (int i = tid; i < 2048; i += 256) {
        int r = i >> 7, col4 = i & 127;
        int4 v = __ldg(&((const int4*)rel_index)[(size_t)(rowblk * 16 + r) * 256 + mhalf * 128 + col4]);
        sidx[r * 512 + col4 * 4 + 0] = (unsigned short)v.x;
        sidx[r * 512 + col4 * 4 + 1] = (unsigned short)v.y;
        sidx[r * 512 + col4 * 4 + 2] = (unsigned short)v.z;
        sidx[r * 512 + col4 * 4 + 3] = (unsigned short)v.w;
    }
    __syncthreads();

    for (int gq = 0; gq < 8; gq++) {
        const int g = blockIdx.z * 8 + gq;
        const float* tbl = &g_tbl2[g][0];
        // gather row-major (coalesced idx runs)
        for (int i = tid; i < 4096; i += 256) {
            int r = i >> 8, c2 = i & 255;
            float b0 = __ldg(tbl + sidx[r * 512 + 2 * c2]);
            float b1 = __ldg(tbl + sidx[r * 512 + 2 * c2 + 1]);
            stage[r * 260 + c2] = __floats2half2_rn(b0, b1);
        }
        __syncthreads();
        // emit fragment-major (conflict-free LDS, coalesced STG.128)
        for (int s = tid; s < 1024; s += 256) {
            int ksgl = s >> 5, lane = s & 31;
            int gid = lane >> 2, l = lane & 3;
            __half2 hA = stage[gid * 260 + ksgl * 8 + l];
            __half2 hB = stage[gid * 260 + ksgl * 8 + l + 4];
            __half2 hC = stage[(gid + 8) * 260 + ksgl * 8 + l];
            __half2 hD = stage[(gid + 8) * 260 + ksgl * 8 + l + 4];
            uint4 o;
            o.x = *(uint*)&hA; o.y = *(uint*)&hB; o.z = *(uint*)&hC; o.w = *(uint*)&hD;
            g_bfrag[g][rowblk][mhalf * 32 + ksgl][lane] = o;
        }
        __syncthreads();
    }
}

// ================= K1: projections via mma.sync fp16 3-pass + GN partials ====
// grid (256 stiles, B, 3 proj), block 256 (8 warps). Tile 128o x 64s, K=128.
// W fragments loaded via 2 coalesced LDG.128 per ks.
__global__ __launch_bounds__(256) void proj_kernel(const float* __restrict__ x)
{
    __shared__ uint Xh[64 * 68];      // [s][c-pair] fp16x2 hi, stride 68 pad
    __shared__ uint Xl[64 * 68];      // lo
    __shared__ float rsum[128], rsq[128];

    const int stile = blockIdx.x, b = blockIdx.y, proj = blockIdx.z;
    const int s0 = stile * 64;
    const int tid = threadIdx.x, wid = tid >> 5, lane = tid & 31;
    const int l = lane & 3, gid = lane >> 2;
    const float* xb = x + (size_t)b * C_ * SPAT;

    // ---- produce X split tiles (transpose c-major -> [s][cp]) ----
    {
        const int s = tid & 63, cpb = tid >> 6;
        #pragma unroll 4
        for (int it = 0; it < 16; it++) {
            int cp = cpb * 16 + it;
            float v0 = xb[(size_t)(2 * cp) * SPAT + s0 + s];
            float v1 = xb[(size_t)(2 * cp + 1) * SPAT + s0 + s];
            uint h2 = cvt_f16x2(v0, v1);
            __half2 hh = *(__half2*)&h2;
            uint l2 = cvt_f16x2(v0 - __low2float(hh), v1 - __high2float(hh));
            Xh[s * 68 + cp] = h2;
            Xl[s * 68 + cp] = l2;
        }
    }
    __syncthreads();

    // ---- mainloop: warp w -> o-rows [w*16, w*16+16), all 64 s ----
    const uint4* wfh = &g_wfh[proj][wid][0][0];
    const uint4* wfl = &g_wfl[proj][wid][0][0];
    const int ob = wid * 16;
    const int row0 = ob + gid, row1 = row0 + 8;

    float acc[8][4];
    #pragma unroll
    for (int i = 0; i < 8; i++)
        #pragma unroll
        for (int j = 0; j < 4; j++) acc[i][j] = 0.f;

    #pragma unroll
    for (int ks = 0; ks < 8; ks++) {
        const int cp0 = ks * 8 + l;
        uint4 H = __ldg(wfh + ks * 32 + lane);
        uint4 L = __ldg(wfl + ks * 32 + lane);
        uint ahi[4] = {H.x, H.y, H.z, H.w};
        uint alo[4] = {L.x, L.y, L.z, L.w};
        #pragma unroll
        for (int nt = 0; nt < 8; nt++) {
            const uint* bp = Xh + (nt * 8 + gid) * 68 + cp0;
            const uint* bq = Xl + (nt * 8 + gid) * 68 + cp0;
            uint b0h = bp[0], b1h = bp[4];
            uint b0l = bq[0], b1l = bq[4];
            mma16816h(acc[nt], ahi, b0h, b1h);
            mma16816h(acc[nt], ahi, b0l, b1l);
            mma16816h(acc[nt], alo, b0h, b1h);
        }
    }

    // ---- epilogue: store y (fp16) + per-row partial stats (from fp32 accs) ----
    __half* y = &g_yh[proj][b][0][0];
    float s_r0 = 0.f, q_r0 = 0.f, s_r1 = 0.f, q_r1 = 0.f;
    #pragma unroll
    for (int nt = 0; nt < 8; nt++) {
        float c0 = acc[nt][0], c1 = acc[nt][1], c2 = acc[nt][2], c3 = acc[nt][3];
        int col = s0 + nt * 8 + 2 * l;
        *(__half2*)&y[(size_t)row0 * SPAT + col] = __floats2half2_rn(c0, c1);
        *(__half2*)&y[(size_t)row1 * SPAT + col] = __floats2half2_rn(c2, c3);
        s_r0 += c0 + c1; q_r0 += c0 * c0 + c1 * c1;
        s_r1 += c2 + c3; q_r1 += c2 * c2 + c3 * c3;
    }
    s_r0 += __shfl_down_sync(0xffffffffu, s_r0, 1);
    s_r0 += __shfl_down_sync(0xffffffffu, s_r0, 2);
    q_r0 += __shfl_down_sync(0xffffffffu, q_r0, 1);
    q_r0 += __shfl_down_sync(0xffffffffu, q_r0, 2);
    s_r1 += __shfl_down_sync(0xffffffffu, s_r1, 1);
    s_r1 += __shfl_down_sync(0xffffffffu, s_r1, 2);
    q_r1 += __shfl_down_sync(0xffffffffu, q_r1, 1);
    q_r1 += __shfl_down_sync(0xffffffffu, q_r1, 2);
    if (l == 0) {
        rsum[row0] = s_r0; rsq[row0] = q_r0;
        rsum[row1] = s_r1; rsq[row1] = q_r1;
    }
    __syncthreads();
    if (tid < 32) {
        float S = rsum[tid * 4] + rsum[tid * 4 + 1] + rsum[tid * 4 + 2] + rsum[tid * 4 + 3];
        float Q = rsq[tid * 4] + rsq[tid * 4 + 1] + rsq[tid * 4 + 2] + rsq[tid * 4 + 3];
        g_part[proj][b][tid][stile][0] = S;
        g_part[proj][b][tid][stile][1] = Q;
    }
}

// ================= K2: finalize GN stats =====================================
__global__ __launch_bounds__(256) void stats_kernel()
{
    const int g = blockIdx.x, b = blockIdx.y, proj = blockIdx.z;
    const int tid = threadIdx.x;
    float s = g_part[proj][b][g][tid][0];
    float q = g_part[proj][b][g][tid][1];
    __shared__ float ss[8], sq[8];
    #pragma unroll
    for (int off = 16; off; off >>= 1) {
        s += __shfl_down_sync(0xffffffffu, s, off);
        q += __shfl_down_sync(0xffffffffu, q, off);
    }
    if ((tid & 31) == 0) { ss[tid >> 5] = s; sq[tid >> 5] = q; }
    __syncthreads();
    if (tid == 0) {
        float S = 0.f, Q = 0.f;
        #pragma unroll
        for (int i = 0; i < 8; i++) { S += ss[i]; Q += sq[i]; }
        const float inv = 1.f / 65536.f;
        float mu  = S * inv;
        float var = Q * inv - mu * mu;
        g_stats[proj][b][g][0] = mu;
        g_stats[proj][b][g][1] = rsqrtf(var + 1e-5f);
    }
}

// ================= K3: normalize + patchify + pool ===========================
__global__ __launch_bounds__(256) void patch_kernel(
    const float* __restrict__ gqg, const float* __restrict__ gqb,
    const float* __restrict__ gkg, const float* __restrict__ gkb,
    const float* __restrict__ gvg, const float* __restrict__ gvb)
{
    const int tid  = threadIdx.x;
    const int unit = blockIdx.x * 4 + (tid >> 6);
    const int n = unit & 1023;
    const int g = (unit >> 10) & 31;
    const int b = unit >> 15;
    const int local = tid & 63;
    const int d = local >> 4, p = local & 15;
    const int c = g * 4 + d;
    const int ti = n >> 8, hi = (n >> 4) & 15, wi = n & 15;
    const int sh = p >> 2, sw = p & 3;
    const int s = ti * 4096 + (hi * 4 + sh) * 64 + wi * 4 + sw;

    const float yq = __half2float(g_yh[0][b][c][s]);
    const float yk = __half2float(g_yh[1][b][c][s]);
    const float yv = __half2float(g_yh[2][b][c][s]);

    float nq = (yq - g_stats[0][b][g][0]) * g_stats[0][b][g][1] * gqg[c] + gqb[c];
    float nk = (yk - g_stats[1][b][g][0]) * g_stats[1][b][g][1] * gkg[c] + gkb[c];
    float nv = (yv - g_stats[2][b][g][0]) * g_stats[2][b][g][1] * gvg[c] + gvb[c];

    g_vf[b][g][n][d * 16 + p] = __float2half(nv);

    #pragma unroll
    for (int off = 8; off; off >>= 1) {
        nq += __shfl_down_sync(0xffffffffu, nq, off);
        nk += __shfl_down_sync(0xffffffffu, nk, off);
    }
    if (p == 0) {
        g_qp[b][g][n][d] = nq * (1.f / 16.f);
        g_kp[b][g][n][d] = nk * (1.f / 16.f);
    }
}

// ================= K3b: vp -> transposed fp16 [dp][m-pair] ===================
__global__ __launch_bounds__(256) void vtrans_kernel()
{
    __shared__ float ts[128][65];
    const int n0 = blockIdx.x * 128, bg = blockIdx.y;
    const int tid = threadIdx.x;
    const __half* vp = &g_vf[0][0][0][0] + (size_t)bg * NTOK * 64;

    for (int i = tid; i < 128 * 64; i += 256) {
        int n = i >> 6, dp = i & 63;
        ts[n][dp] = __half2float(vp[(size_t)(n0 + n) * 64 + dp]);
    }
    __syncthreads();
    for (int i = tid; i < 64 * 64; i += 256) {
        int dp = i >> 6, j = i & 63;
        float v0 = ts[2 * j][dp], v1 = ts[2 * j + 1][dp];
        g_vh[bg][dp][(n0 >> 1) + j] = cvt_f16x2(v0, v1);
    }
}

// ================= K4: attention via mma.sync fp16 (single pass) =============
// grid (8 mtiles, 32 g, 2 b), block 256 (8 warps). 128 rows/CTA, 16 rows/warp.
// Bias from fragment-major g_bfrag: ONE coalesced LDG.128 per ks.
// smem: kp 16KB | q 2KB | Vh 17408B = 35840B -> 3 CTAs/SM
#define ATT_SMEM 35840

__global__ __launch_bounds__(256, 3) void attn_kernel(float* __restrict__ out)
{
    extern __shared__ float smem[];
    float4* kp_s = (float4*)smem;               // 1024 float4
    float4* q_s  = (float4*)(smem + 4096);      // 128 float4 (prescaled)
    uint*   vhs  = (uint*)(smem + 4608);        // 64 rows x 68 u32 (stride pad)

    const int mtile = blockIdx.x, g = blockIdx.y, b = blockIdx.z;
    const int n0 = mtile * 128;
    const int bg = b * 32 + g;
    const int tid = threadIdx.x, wid = tid >> 5, lane = tid & 31;
    const int l = lane & 3, gid = lane >> 2;

    {
        const float4* kp = (const float4*)&g_kp[b][g][0][0];
        for (int i = tid; i < 1024; i += 256) kp_s[i] = kp[i];
        const float4* qp = (const float4*)&g_qp[b][g][0][0];
        const float QS = 0.72134752044448170f;   // 0.5 * log2(e)
        for (int i = tid; i < 128; i += 256) {
            float4 q = qp[n0 + i];
            q.x *= QS; q.y *= QS; q.z *= QS; q.w *= QS;
            q_s[i] = q;
        }
    }
    __syncthreads();

    const int rb = wid * 16;
    float4 q0 = q_s[rb + gid], q1 = q_s[rb + gid + 8];
    ull q0x = pack2(q0.x), q0y = pack2(q0.y), q0z = pack2(q0.z), q0w = pack2(q0.w);
    ull q1x = pack2(q1.x), q1y = pack2(q1.y), q1z = pack2(q1.z), q1w = pack2(q1.w);
    const uint4* bfp = &g_bfrag[g][mtile * 8 + wid][0][lane];

    float acc[8][4];
    #pragma unroll
    for (int i = 0; i < 8; i++)
        #pragma unroll
        for (int j = 0; j < 4; j++) acc[i][j] = 0.f;
    float s0 = 0.f, s1 = 0.f;

    for (int c = 0; c < 8; c++) {
        __syncthreads();
        for (int i = tid; i < 1024; i += 256) {
            int dp = i >> 4, j4 = i & 15;
            float4 vh = *(const float4*)&g_vh[bg][dp][c * 64 + j4 * 4];
            *(float4*)&vhs[dp * 68 + j4 * 4] = vh;
        }
        __syncthreads();

        #pragma unroll
        for (int ks = 0; ks < 8; ks++) {
            const int m00 = c * 128 + ks * 16 + 2 * l;
            float4 kv00 = kp_s[m00],     kv01 = kp_s[m00 + 1];
            float4 kv10 = kp_s[m00 + 8], kv11 = kp_s[m00 + 9];

            uint4 bv = __ldg(bfp + (c * 8 + ks) * 32);
            float2 fA = __half22float2(*(__half2*)&bv.x);
            float2 fB = __half22float2(*(__half2*)&bv.y);
            float2 fC = __half22float2(*(__half2*)&bv.z);
            float2 fD = __half22float2(*(__half2*)&bv.w);
            ull d0a = packf2(fA.x, fA.y);
            ull d0b = packf2(fB.x, fB.y);
            ull d1a = packf2(fC.x, fC.y);
            ull d1b = packf2(fD.x, fD.y);

            ull kax = packf2(kv00.x, kv01.x), kay = packf2(kv00.y, kv01.y);
            ull kaz = packf2(kv00.z, kv01.z), kaw = packf2(kv00.w, kv01.w);
            ull kbx = packf2(kv10.x, kv11.x), kby = packf2(kv10.y, kv11.y);
            ull kbz = packf2(kv10.z, kv11.z), kbw = packf2(kv10.w, kv11.w);

            ffma2(d0a, q0x, kax); ffma2(d0a, q0y, kay); ffma2(d0a, q0z, kaz); ffma2(d0a, q0w, kaw);
            ffma2(d0b, q0x, kbx); ffma2(d0b, q0y, kby); ffma2(d0b, q0z, kbz); ffma2(d0b, q0w, kbw);
            ffma2(d1a, q1x, kax); ffma2(d1a, q1y, kay); ffma2(d1a, q1z, kaz); ffma2(d1a, q1w, kaw);
            ffma2(d1b, q1x, kbx); ffma2(d1b, q1y, kby); ffma2(d1b, q1z, kbz); ffma2(d1b, q1w, kbw);

            float2 f0a = unpack2(d0a), f0b = unpack2(d0b);
            float2 f1a = unpack2(d1a), f1b = unpack2(d1b);
            float e00 = ex2f(f0a.x), e01 = ex2f(f0a.y), e02 = ex2f(f0b.x), e03 = ex2f(f0b.y);
            float e10 = ex2f(f1a.x), e11 = ex2f(f1a.y), e12 = ex2f(f1b.x), e13 = ex2f(f1b.y);
            s0 += (e00 + e01) + (e02 + e03);
            s1 += (e10 + e11) + (e12 + e13);

            uint ah[4];
            ah[0] = cvt_f16x2(e00, e01);
            ah[1] = cvt_f16x2(e10, e11);
            ah[2] = cvt_f16x2(e02, e03);
            ah[3] = cvt_f16x2(e12, e13);

            const uint* bh = vhs + ks * 8 + l;
            #pragma unroll
            for (int nb = 0; nb < 8; nb++) {
                int ro = (nb * 8 + gid) * 68;
                mma16816h(acc[nb], ah, bh[ro], bh[ro + 4]);
            }
        }
    }

    s0 += __shfl_xor_sync(0xffffffffu, s0, 1);
    s0 += __shfl_xor_sync(0xffffffffu, s0, 2);
    s1 += __shfl_xor_sync(0xffffffffu, s1, 1);
    s1 += __shfl_xor_sync(0xffffffffu, s1, 2);
    const float inv0 = 1.f / s0, inv1 = 1.f / s1;

    const int nrow0 = n0 + rb + gid, nrow1 = nrow0 + 8;
    const int ti0 = nrow0 >> 8, hi0 = (nrow0 >> 4) & 15, wi0 = nrow0 & 15;
    const int ti1 = nrow1 >> 8, hi1 = (nrow1 >> 4) & 15, wi1 = nrow1 & 15;
    #pragma unroll
    for (int nb = 0; nb < 8; nb++) {
        const int dp = nb * 8 + 2 * l;
        const int d = dp >> 4, p = dp & 15, sh = p >> 2, sw = p & 3;
        const int cch = (b * 128 + g * 4 + d);
        size_t o0 = ((size_t)(cch * 4 + ti0) * 64 + hi0 * 4 + sh) * 64 + wi0 * 4 + sw;
        size_t o1 = ((size_t)(cch * 4 + ti1) * 64 + hi1 * 4 + sh) * 64 + wi1 * 4 + sw;
        float2 v0 = make_float2(acc[nb][0] * inv0, acc[nb][1] * inv0);
        float2 v1 = make_float2(acc[nb][2] * inv1, acc[nb][3] * inv1);
        *(float2*)&out[o0] = v0;
        *(float2*)&out[o1] = v1;
    }
}

// ============================ launcher =======================================
extern "C" void kernel_launch(void* const* d_in, const int* in_sizes, int n_in,
                              void* d_out, int out_size)
{
    const float* x   = (const float*)d_in[0];
    const float* Wq  = (const float*)d_in[1];
    const float* Wk  = (const float*)d_in[2];
    const float* Wv  = (const float*)d_in[3];
    const float* gqg = (const float*)d_in[4];
    const float* gqb = (const float*)d_in[5];
    const float* gkg = (const float*)d_in[6];
    const float* gkb = (const float*)d_in[7];
    const float* gvg = (const float*)d_in[8];
    const float* gvb = (const float*)d_in[9];
    const float* rel_table = (const float*)d_in[10];
    const int*   rel_index = (const int*)d_in[11];
    float* out = (float*)d_out;

    cudaFuncSetAttribute(attn_kernel, cudaFuncAttributeMaxDynamicSharedMemorySize, ATT_SMEM);

    wprep_kernel<<<3, 256>>>(Wq, Wk, Wv);
    wfrag_kernel<<<dim3(3, 8), 256>>>();
    tblprep_kernel<<<NH_, 256>>>(rel_table);
    bexp_kernel<<<dim3(64, 2, 4), 256, BEXP_SMEM>>>(rel_index);
    proj_kernel<<<dim3(256, B_, 3), 256>>>(x);
    stats_kernel<<<dim3(NH_, B_, 3), 256>>>();
    patch_kernel<<<16384, 256>>>(gqg, gqb, gkg, gkb, gvg, gvb);
    vtrans_kernel<<<dim3(8, 64), 256>>>();
    attn_kernel<<<dim3(8, NH_, B_), 256, ATT_SMEM>>>(out);
}